// round 14
// baseline (speedup 1.0000x reference)
#include <cuda_runtime.h>
#include <cuda_fp16.h>
#include <math.h>
#include <stdint.h>

// Problem constants
#define T_       1024
#define D_       1024
#define E_       16
#define K_SEL    4
#define NGRP     4
#define INTER_   512
#define SH_INTER 1024
#define RSCALE   2.5f

#define LDH   40                      // smem row stride in halves (80B, LDSM conflict-free)
#define PLANE (128 * LDH)             // halves per plane-stage
#define ABYTES (PLANE * 2)            // 10240 B
#define NSTG  3
#define SMEM_BYTES (2 * NSTG * ABYTES)   // 61440 B

// ---------------- device scratch (fp16 operands) ----------------
__device__ int    g_cnt[E_];
__device__ int    g_tok[E_ * T_];
__device__ float  g_wt [E_ * T_];
__device__ __half h_x [(size_t)T_ * D_];
__device__ __half h_gp[(size_t)E_ * INTER_ * D_];
__device__ __half h_up[(size_t)E_ * INTER_ * D_];
__device__ __half h_dp[(size_t)E_ * D_ * INTER_];
__device__ __half h_sg[(size_t)SH_INTER * D_];
__device__ __half h_su[(size_t)SH_INTER * D_];
__device__ __half h_sd[(size_t)D_ * SH_INTER];
__device__ __half g_inter[(size_t)E_ * T_ * INTER_];
__device__ __half g_hsh[(size_t)T_ * SH_INTER];

// ---------------- helpers ----------------
__device__ __forceinline__ uint32_t smem_u32(const void* p) {
    uint32_t a;
    asm("{ .reg .u64 t; cvta.to.shared.u64 t, %1; cvt.u32.u64 %0, t; }" : "=r"(a) : "l"(p));
    return a;
}
__device__ __forceinline__ void cp16(uint32_t s, const void* g) {
    asm volatile("cp.async.cg.shared.global [%0], [%1], 16;" :: "r"(s), "l"(g) : "memory");
}
#define CP_COMMIT() asm volatile("cp.async.commit_group;" ::: "memory")
#define CP_WAIT(n)  asm volatile("cp.async.wait_group %0;" :: "n"(n) : "memory")

__device__ __forceinline__ void ldsm4(uint32_t& r0, uint32_t& r1, uint32_t& r2, uint32_t& r3,
                                      uint32_t addr) {
    asm volatile("ldmatrix.sync.aligned.m8n8.x4.shared.b16 {%0,%1,%2,%3}, [%4];"
                 : "=r"(r0), "=r"(r1), "=r"(r2), "=r"(r3) : "r"(addr));
}
__device__ __forceinline__ void mma_f16(float c[4],
                                        uint32_t a0, uint32_t a1, uint32_t a2, uint32_t a3,
                                        uint32_t b0, uint32_t b1) {
    asm volatile(
        "mma.sync.aligned.m16n8k16.row.col.f32.f16.f16.f32 "
        "{%0,%1,%2,%3}, {%4,%5,%6,%7}, {%8,%9}, {%0,%1,%2,%3};"
        : "+f"(c[0]), "+f"(c[1]), "+f"(c[2]), "+f"(c[3])
        : "r"(a0), "r"(a1), "r"(a2), "r"(a3), "r"(b0), "r"(b1));
}
__device__ __forceinline__ float silu_mul(float g, float u) {
    return g / (1.f + expf(-g)) * u;
}
// vector no-return reduction: one red.global.v2 per float2
__device__ __forceinline__ void red_add_v2(float* addr, float a, float b) {
    asm volatile("red.global.add.v2.f32 [%0], {%1, %2};"
                 :: "l"(addr), "f"(a), "f"(b) : "memory");
}

// ---------------- fused fp32 -> fp16 conversion ----------------
#define BIG8   (E_ * INTER_ * D_ / 8)
#define HBIG8  (BIG8 / 2)
#define SML8   (SH_INTER * D_ / 8)

__device__ __forceinline__ void cvt_chunk(const float* s, __half* d, int i) {
    float4 v0 = ((const float4*)s)[2 * i];
    float4 v1 = ((const float4*)s)[2 * i + 1];
    ((__half2*)d)[4 * i + 0] = __floats2half2_rn(v0.x, v0.y);
    ((__half2*)d)[4 * i + 1] = __floats2half2_rn(v0.z, v0.w);
    ((__half2*)d)[4 * i + 2] = __floats2half2_rn(v1.x, v1.y);
    ((__half2*)d)[4 * i + 3] = __floats2half2_rn(v1.z, v1.w);
}

// chunk 0: x + first-half gp/up (experts 0..7)
#define C08 (SML8 + 2 * HBIG8)
__global__ void cvt_c0_kernel(const float* __restrict__ x, const float* __restrict__ gp,
                              const float* __restrict__ up) {
    int i = blockIdx.x * blockDim.x + threadIdx.x;
    if (i >= C08) return;
    if (i < SML8)                cvt_chunk(x,  h_x,  i);
    else if (i < SML8 + HBIG8)   cvt_chunk(gp, h_gp, i - SML8);
    else                         cvt_chunk(up, h_up, i - SML8 - HBIG8);
}
// chunk 1: second-half gp/up (experts 8..15)
__global__ void cvt_c1_kernel(const float* __restrict__ gp, const float* __restrict__ up) {
    int i = blockIdx.x * blockDim.x + threadIdx.x;
    if (i >= 2 * HBIG8) return;
    if (i < HBIG8) cvt_chunk(gp, h_gp, i + HBIG8);
    else           cvt_chunk(up, h_up, (i - HBIG8) + HBIG8);
}
// shared gu-side: sg, su
__global__ void cvt_sgsu_kernel(const float* __restrict__ sg, const float* __restrict__ su) {
    int i = blockIdx.x * blockDim.x + threadIdx.x;
    if (i >= 2 * SML8) return;
    if (i < SML8) cvt_chunk(sg, h_sg, i);
    else          cvt_chunk(su, h_su, i - SML8);
}
// down-side: dp, sd
#define DW8 (BIG8 + SML8)
__global__ void cvt_dw_kernel(const float* __restrict__ dp, const float* __restrict__ sd) {
    int i = blockIdx.x * blockDim.x + threadIdx.x;
    if (i >= DW8) return;
    if (i < BIG8) cvt_chunk(dp, h_dp, i);
    else          cvt_chunk(sd, h_sd, i - BIG8);
}

// ---------------- routing ----------------
__global__ void zero_counts_kernel() {
    if (threadIdx.x < E_) g_cnt[threadIdx.x] = 0;
}

__global__ void route_kernel(const float* __restrict__ x,
                             const float* __restrict__ gw,
                             const float* __restrict__ gb) {
    const int t = blockIdx.x;
    __shared__ float xs[D_];
    __shared__ float sc[E_];
    const int tid = threadIdx.x;  // 128
    const float4* xr = (const float4*)(x + (size_t)t * D_);
    float4* xs4 = (float4*)xs;
    for (int i = tid; i < D_ / 4; i += 128) xs4[i] = xr[i];
    __syncthreads();

    const int warp = tid >> 5, lane = tid & 31;
    for (int e = warp * 4; e < warp * 4 + 4; e++) {
        const float* w = gw + (size_t)e * D_;
        float p = 0.f;
        for (int j = lane; j < D_; j += 32) p += xs[j] * w[j];
        #pragma unroll
        for (int o = 16; o; o >>= 1) p += __shfl_xor_sync(0xffffffffu, p, o);
        if (lane == 0) sc[e] = 1.f / (1.f + expf(-p));
    }
    __syncthreads();

    if (tid == 0) {
        float s[E_];
        #pragma unroll
        for (int e = 0; e < E_; e++) s[e] = sc[e] + gb[e];
        float gsc[NGRP];
        #pragma unroll
        for (int g = 0; g < NGRP; g++) {
            float m1 = -1e30f, m2 = -1e30f;
            #pragma unroll
            for (int j = 0; j < 4; j++) {
                float v = s[g * 4 + j];
                if (v > m1) { m2 = m1; m1 = v; } else if (v > m2) { m2 = v; }
            }
            gsc[g] = m1 + m2;
        }
        int g1 = 0;
        for (int g = 1; g < NGRP; g++) if (gsc[g] > gsc[g1]) g1 = g;
        int g2 = -1;
        for (int g = 0; g < NGRP; g++) {
            if (g == g1) continue;
            if (g2 < 0 || gsc[g] > gsc[g2]) g2 = g;
        }
        float masked[E_];
        #pragma unroll
        for (int e = 0; e < E_; e++) {
            int g = e >> 2;
            masked[e] = (g == g1 || g == g2) ? s[e] : 0.f;
        }
        int idx[K_SEL];
        float w[K_SEL];
        bool used[E_];
        #pragma unroll
        for (int e = 0; e < E_; e++) used[e] = false;
        float wsum = 0.f;
        for (int k = 0; k < K_SEL; k++) {
            int best = -1; float bv = -1e30f;
            for (int e = 0; e < E_; e++) {
                if (used[e]) continue;
                if (masked[e] > bv) { bv = masked[e]; best = e; }
            }
            used[best] = true;
            idx[k] = best;
            w[k] = sc[best];
            wsum += w[k];
        }
        const float scale = RSCALE / wsum;
        for (int k = 0; k < K_SEL; k++) {
            int e = idx[k];
            int pos = atomicAdd(&g_cnt[e], 1);
            g_tok[e * T_ + pos] = t;
            g_wt [e * T_ + pos] = w[k] * scale;
        }
    }
}

// ================================================================
// GEMM 1 (fp16 + ldmatrix + 3-stage single-barrier pipeline)
// zoff selects slice range: z < 16 routed expert, z >= 16 shared half.
// ================================================================
__global__ void __launch_bounds__(256, 2) mma_gu_kernel(int zoff) {
    const int z = zoff + blockIdx.z;
    const bool routed = z < E_;
    const int cnt = routed ? g_cnt[z] : T_;
    const int m0  = blockIdx.y * 128;
    if (m0 >= cnt) return;
    const int n0 = blockIdx.x * 64;

    const __half* Wg;
    const __half* Wu;
    __half* C;
    int ldc, cb;
    if (routed) {
        Wg = h_gp + ((size_t)z * INTER_ + n0) * D_;
        Wu = h_up + ((size_t)z * INTER_ + n0) * D_;
        C = g_inter + (size_t)z * T_ * INTER_;
        ldc = INTER_; cb = n0;
    } else {
        const int h = z - E_;
        Wg = h_sg + ((size_t)h * 512 + n0) * D_;
        Wu = h_su + ((size_t)h * 512 + n0) * D_;
        C = g_hsh;
        ldc = SH_INTER; cb = h * 512 + n0;
    }

    extern __shared__ __half smem[];
    __half* As = smem;
    __half* Bs = smem + NSTG * PLANE;
    const uint32_t sA = smem_u32(As);
    const uint32_t sB = smem_u32(Bs);

    const int tid = threadIdx.x, wid = tid >> 5, lane = tid & 31;
    const int wm = wid >> 2, wn = wid & 3;

    const __half* agl[2]; const __half* bgl[2];
    uint32_t sa[2], sbo[2];
    #pragma unroll
    for (int t = 0; t < 2; t++) {
        int it = tid + 256 * t;
        int row = it >> 2, c4 = it & 3;
        int mm = m0 + row; if (mm > cnt - 1) mm = cnt - 1;
        int ar = routed ? g_tok[z * T_ + mm] : mm;
        agl[t] = h_x + (size_t)ar * D_ + c4 * 8;
        bgl[t] = ((row < 64) ? (Wg + (size_t)row * D_) : (Wu + (size_t)(row - 64) * D_)) + c4 * 8;
        sa[t]  = sA + (uint32_t)(row * LDH + c4 * 8) * 2u;
        sbo[t] = sB + (uint32_t)(row * LDH + c4 * 8) * 2u;
    }

    const int alr = lane & 15, alk = (lane >> 4) * 8;
    const uint32_t a_lsm = sA + (uint32_t)(((wm * 64 + alr) * LDH) + alk) * 2u;
    const int bnr = ((lane >> 4) & 1) * 8 + (lane & 7), bkc = ((lane >> 3) & 1) * 8;
    const uint32_t bg_lsm = sB + (uint32_t)(((wn * 16 + bnr) * LDH) + bkc) * 2u;
    const uint32_t bu_lsm = sB + (uint32_t)(((wn * 16 + bnr + 64) * LDH) + bkc) * 2u;

    float acg[4][2][4], acu[4][2][4];
    #pragma unroll
    for (int mi = 0; mi < 4; mi++)
        #pragma unroll
        for (int nj = 0; nj < 2; nj++)
            #pragma unroll
            for (int r = 0; r < 4; r++) { acg[mi][nj][r] = 0.f; acu[mi][nj][r] = 0.f; }

    const int NS = D_ / 32;   // 32 stages

    #pragma unroll
    for (int p = 0; p < 2; p++) {
        const uint32_t bo = (uint32_t)(p * ABYTES);
        #pragma unroll
        for (int t = 0; t < 2; t++) { cp16(sa[t] + bo, agl[t] + p * 32); cp16(sbo[t] + bo, bgl[t] + p * 32); }
        CP_COMMIT();
    }

    int buf = 0, pbuf = 2;
    for (int s = 0; s < NS; s++) {
        if (s + 1 < NS) CP_WAIT(1); else CP_WAIT(0);
        __syncthreads();
        if (s + 2 < NS) {
            const uint32_t bo = (uint32_t)(pbuf * ABYTES);
            #pragma unroll
            for (int t = 0; t < 2; t++) {
                cp16(sa[t] + bo, agl[t] + (s + 2) * 32);
                cp16(sbo[t] + bo, bgl[t] + (s + 2) * 32);
            }
            CP_COMMIT();
        }

        const uint32_t po = (uint32_t)(buf * ABYTES);
        #pragma unroll
        for (int ks = 0; ks < 2; ks++) {
            const uint32_t ko = (uint32_t)(ks * 32);
            uint32_t af[4][4];
            #pragma unroll
            for (int mi = 0; mi < 4; mi++)
                ldsm4(af[mi][0], af[mi][1], af[mi][2], af[mi][3],
                      a_lsm + po + ko + (uint32_t)(mi * 16 * LDH * 2));
            uint32_t bg0a, bg1a, bg0b, bg1b, bu0a, bu1a, bu0b, bu1b;
            ldsm4(bg0a, bg1a, bg0b, bg1b, bg_lsm + po + ko);
            ldsm4(bu0a, bu1a, bu0b, bu1b, bu_lsm + po + ko);
            #pragma unroll
            for (int mi = 0; mi < 4; mi++) {
                mma_f16(acg[mi][0], af[mi][0], af[mi][1], af[mi][2], af[mi][3], bg0a, bg1a);
                mma_f16(acg[mi][1], af[mi][0], af[mi][1], af[mi][2], af[mi][3], bg0b, bg1b);
                mma_f16(acu[mi][0], af[mi][0], af[mi][1], af[mi][2], af[mi][3], bu0a, bu1a);
                mma_f16(acu[mi][1], af[mi][0], af[mi][1], af[mi][2], af[mi][3], bu0b, bu1b);
            }
        }
        buf = (buf == NSTG - 1) ? 0 : buf + 1;
        pbuf = (pbuf == NSTG - 1) ? 0 : pbuf + 1;
    }

    const int q = lane >> 2, c2 = (lane & 3) * 2;
    #pragma unroll
    for (int mi = 0; mi < 4; mi++) {
        const int r0 = m0 + wm * 64 + mi * 16 + q;
        #pragma unroll
        for (int nj = 0; nj < 2; nj++) {
            const int col = cb + wn * 16 + nj * 8 + c2;
            if (r0 < cnt) {
                *(__half2*)(C + (size_t)r0 * ldc + col) =
                    __floats2half2_rn(silu_mul(acg[mi][nj][0], acu[mi][nj][0]),
                                      silu_mul(acg[mi][nj][1], acu[mi][nj][1]));
            }
            if (r0 + 8 < cnt) {
                *(__half2*)(C + (size_t)(r0 + 8) * ldc + col) =
                    __floats2half2_rn(silu_mul(acg[mi][nj][2], acu[mi][nj][2]),
                                      silu_mul(acg[mi][nj][3], acu[mi][nj][3]));
            }
        }
    }
}

// ================================================================
// GEMM 2 (fp16 + ldmatrix + 3-stage single-barrier pipeline)
// epilogue: red.global.add.v2.f32 (vector no-return reductions)
// ================================================================
__global__ void __launch_bounds__(256, 2) mma_down_kernel(int zoff, float* __restrict__ out) {
    const int z = zoff + blockIdx.z;
    const bool routed = z < E_;
    const int cnt = routed ? g_cnt[z] : T_;
    const int m0  = blockIdx.y * 128;
    if (m0 >= cnt) return;
    const int n0 = blockIdx.x * 128;

    const __half* A;
    const __half* W;
    int lda, ldw;
    if (routed) {
        A = g_inter + (size_t)z * T_ * INTER_; lda = INTER_;
        W = h_dp + (size_t)z * D_ * INTER_;    ldw = INTER_;
    } else {
        const int h = z - E_;
        A = g_hsh + (size_t)h * 512; lda = SH_INTER;
        W = h_sd  + (size_t)h * 512; ldw = SH_INTER;
    }

    extern __shared__ __half smem[];
    __half* As = smem;
    __half* Bs = smem + NSTG * PLANE;
    const uint32_t sA = smem_u32(As);
    const uint32_t sB = smem_u32(Bs);

    const int tid = threadIdx.x, wid = tid >> 5, lane = tid & 31;
    const int wm = wid >> 2, wn = wid & 3;

    const __half* agl[2]; const __half* bgl[2];
    uint32_t sa[2], sbo[2];
    #pragma unroll
    for (int t = 0; t < 2; t++) {
        int it = tid + 256 * t;
        int row = it >> 2, c4 = it & 3;
        int mm = m0 + row; if (mm > cnt - 1) mm = cnt - 1;
        agl[t] = A + (size_t)mm * lda + c4 * 8;
        bgl[t] = W + (size_t)(n0 + row) * ldw + c4 * 8;
        sa[t]  = sA + (uint32_t)(row * LDH + c4 * 8) * 2u;
        sbo[t] = sB + (uint32_t)(row * LDH + c4 * 8) * 2u;
    }

    const int alr = lane & 15, alk = (lane >> 4) * 8;
    const uint32_t a_lsm = sA + (uint32_t)(((wm * 64 + alr) * LDH) + alk) * 2u;
    const int bnr = ((lane >> 4) & 1) * 8 + (lane & 7), bkc = ((lane >> 3) & 1) * 8;
    const uint32_t b_lsm = sB + (uint32_t)(((wn * 32 + bnr) * LDH) + bkc) * 2u;

    float acc[4][4][4];
    #pragma unroll
    for (int mi = 0; mi < 4; mi++)
        #pragma unroll
        for (int nj = 0; nj < 4; nj++)
            #pragma unroll
            for (int r = 0; r < 4; r++) acc[mi][nj][r] = 0.f;

    const int NS = INTER_ / 32;   // 16 stages

    #pragma unroll
    for (int p = 0; p < 2; p++) {
        const uint32_t bo = (uint32_t)(p * ABYTES);
        #pragma unroll
        for (int t = 0; t < 2; t++) { cp16(sa[t] + bo, agl[t] + p * 32); cp16(sbo[t] + bo, bgl[t] + p * 32); }
        CP_COMMIT();
    }

    int buf = 0, pbuf = 2;
    for (int s = 0; s < NS; s++) {
        if (s + 1 < NS) CP_WAIT(1); else CP_WAIT(0);
        __syncthreads();
        if (s + 2 < NS) {
            const uint32_t bo = (uint32_t)(pbuf * ABYTES);
            #pragma unroll
            for (int t = 0; t < 2; t++) {
                cp16(sa[t] + bo, agl[t] + (s + 2) * 32);
                cp16(sbo[t] + bo, bgl[t] + (s + 2) * 32);
            }
            CP_COMMIT();
        }

        const uint32_t po = (uint32_t)(buf * ABYTES);
        #pragma unroll
        for (int ks = 0; ks < 2; ks++) {
            const uint32_t ko = (uint32_t)(ks * 32);
            uint32_t af[4][4];
            #pragma unroll
            for (int mi = 0; mi < 4; mi++)
                ldsm4(af[mi][0], af[mi][1], af[mi][2], af[mi][3],
                      a_lsm + po + ko + (uint32_t)(mi * 16 * LDH * 2));
            uint32_t b[4][2];
            ldsm4(b[0][0], b[0][1], b[1][0], b[1][1], b_lsm + po + ko);
            ldsm4(b[2][0], b[2][1], b[3][0], b[3][1], b_lsm + po + ko + (uint32_t)(16 * LDH * 2));
            #pragma unroll
            for (int nj = 0; nj < 4; nj++)
                #pragma unroll
                for (int mi = 0; mi < 4; mi++)
                    mma_f16(acc[mi][nj], af[mi][0], af[mi][1], af[mi][2], af[mi][3],
                            b[nj][0], b[nj][1]);
        }
        buf = (buf == NSTG - 1) ? 0 : buf + 1;
        pbuf = (pbuf == NSTG - 1) ? 0 : pbuf + 1;
    }

    const int q = lane >> 2, c2 = (lane & 3) * 2;
    #pragma unroll
    for (int mi = 0; mi < 4; mi++) {
        #pragma unroll
        for (int half_ = 0; half_ < 2; half_++) {
            const int m = m0 + wm * 64 + mi * 16 + q + half_ * 8;
            if (m >= cnt) continue;
            const int   tok = routed ? g_tok[z * T_ + m] : m;
            const float wt  = routed ? g_wt [z * T_ + m] : 1.f;
            float* op = out + (size_t)tok * D_;
            #pragma unroll
            for (int nj = 0; nj < 4; nj++) {
                const int col = n0 + wn * 32 + nj * 8 + c2;
                red_add_v2(op + col, wt * acc[mi][nj][half_ * 2 + 0],
                                     wt * acc[mi][nj][half_ * 2 + 1]);
            }
        }
    }
}

// ---------------- launch (chunked convert + dual-pipeline fork/join) ----------------
extern "C" void kernel_launch(void* const* d_in, const int* in_sizes, int n_in,
                              void* d_out, int out_size) {
    const float* x  = (const float*)d_in[0];
    const float* gw = (const float*)d_in[2];
    const float* gb = (const float*)d_in[3];
    const float* gp = (const float*)d_in[4];
    const float* up = (const float*)d_in[5];
    const float* dp = (const float*)d_in[6];
    const float* sg = (const float*)d_in[7];
    const float* su = (const float*)d_in[8];
    const float* sd = (const float*)d_in[9];
    float* out = (float*)d_out;

    cudaFuncSetAttribute(mma_gu_kernel,   cudaFuncAttributeMaxDynamicSharedMemorySize, SMEM_BYTES);
    cudaFuncSetAttribute(mma_down_kernel, cudaFuncAttributeMaxDynamicSharedMemorySize, SMEM_BYTES);

    cudaStream_t s1, s2, s3, s4;
    cudaStreamCreateWithFlags(&s1, cudaStreamNonBlocking);
    cudaStreamCreateWithFlags(&s2, cudaStreamNonBlocking);
    cudaStreamCreateWithFlags(&s3, cudaStreamNonBlocking);
    cudaStreamCreateWithFlags(&s4, cudaStreamNonBlocking);
    cudaEvent_t eF, eDW, eRoute, eC0, eC1, eShared;
    cudaEventCreateWithFlags(&eF,     cudaEventDisableTiming);
    cudaEventCreateWithFlags(&eDW,    cudaEventDisableTiming);
    cudaEventCreateWithFlags(&eRoute, cudaEventDisableTiming);
    cudaEventCreateWithFlags(&eC0,    cudaEventDisableTiming);
    cudaEventCreateWithFlags(&eC1,    cudaEventDisableTiming);
    cudaEventCreateWithFlags(&eShared,cudaEventDisableTiming);

    const int NB = 256;

    // fork
    cudaEventRecord(eF, 0);
    cudaStreamWaitEvent(s1, eF, 0);
    cudaStreamWaitEvent(s2, eF, 0);
    cudaStreamWaitEvent(s3, eF, 0);
    cudaStreamWaitEvent(s4, eF, 0);

    // s1: memset + down-side weight convert (hidden under gu stage)
    cudaMemsetAsync(out, 0, (size_t)T_ * D_ * sizeof(float), s1);
    cvt_dw_kernel<<<(DW8 + NB - 1) / NB, NB, 0, s1>>>(dp, sd);
    cudaEventRecord(eDW, s1);

    // s2: routing (hidden under gu-side convert)
    zero_counts_kernel<<<1, 32, 0, s2>>>();
    route_kernel<<<T_, 128, 0, s2>>>(x, gw, gb);
    cudaEventRecord(eRoute, s2);

    // s0 (capture stream): routed pipeline, convert chunked
    cvt_c0_kernel<<<(C08 + NB - 1) / NB, NB>>>(x, gp, up);
    cudaEventRecord(eC0, 0);

    // s4: second convert chunk, concurrent with first gu slice
    cudaStreamWaitEvent(s4, eC0, 0);
    cvt_c1_kernel<<<(2 * HBIG8 + NB - 1) / NB, NB, 0, s4>>>(gp, up);
    cudaEventRecord(eC1, s4);

    // s0: gu slice 0 (experts 0..7) right after c0 + route
    cudaStreamWaitEvent(0, eRoute, 0);
    mma_gu_kernel<<<dim3(INTER_ / 64, T_ / 128, 8), 256, SMEM_BYTES>>>(0);
    // gu slice 1 (experts 8..15) after c1
    cudaStreamWaitEvent(0, eC1, 0);
    mma_gu_kernel<<<dim3(INTER_ / 64, T_ / 128, 8), 256, SMEM_BYTES>>>(8);
    // routed down
    cudaStreamWaitEvent(0, eDW, 0);
    mma_down_kernel<<<dim3(D_ / 128, T_ / 128, E_), 256, SMEM_BYTES>>>(0, out);

    // s3: shared pipeline (concurrent with routed pipeline)
    cvt_sgsu_kernel<<<(2 * SML8 + NB - 1) / NB, NB, 0, s3>>>(sg, su);
    cudaStreamWaitEvent(s3, eC0, 0);                 // needs converted x
    mma_gu_kernel<<<dim3(8, T_ / 128, 2), 256, SMEM_BYTES, s3>>>(E_);
    cudaStreamWaitEvent(s3, eDW, 0);                 // needs sd + memset
    mma_down_kernel<<<dim3(D_ / 128, T_ / 128, 2), 256, SMEM_BYTES, s3>>>(E_, out);
    cudaEventRecord(eShared, s3);

    // join shared pipeline back into capture stream
    cudaStreamWaitEvent(0, eShared, 0);

    cudaEventDestroy(eF);
    cudaEventDestroy(eDW);
    cudaEventDestroy(eRoute);
    cudaEventDestroy(eC0);
    cudaEventDestroy(eC1);
    cudaEventDestroy(eShared);
    cudaStreamDestroy(s1);
    cudaStreamDestroy(s2);
    cudaStreamDestroy(s3);
    cudaStreamDestroy(s4);
}

// round 15
// speedup vs baseline: 1.1610x; 1.1610x over previous
#include <cuda_runtime.h>
#include <cuda_fp16.h>
#include <math.h>
#include <stdint.h>

// Problem constants
#define T_       1024
#define D_       1024
#define E_       16
#define K_SEL    4
#define NGRP     4
#define INTER_   512
#define SH_INTER 1024
#define RSCALE   2.5f

#define LDH   40                      // smem row stride in halves (80B, LDSM conflict-free)
#define PLANE (128 * LDH)             // halves per plane-stage
#define ABYTES (PLANE * 2)            // 10240 B
#define NSTG  5                       // 5-deep cp.async ring
#define PRE   4                       // prologue depth (NSTG-1)
#define SMEM_BYTES (2 * NSTG * ABYTES)   // 102400 B

// ---------------- device scratch (fp16 operands) ----------------
__device__ int    g_cnt[E_];
__device__ int    g_tok[E_ * T_];
__device__ float  g_wt [E_ * T_];
__device__ __half h_x [(size_t)T_ * D_];
__device__ __half h_gp[(size_t)E_ * INTER_ * D_];
__device__ __half h_up[(size_t)E_ * INTER_ * D_];
__device__ __half h_dp[(size_t)E_ * D_ * INTER_];
__device__ __half h_sg[(size_t)SH_INTER * D_];
__device__ __half h_su[(size_t)SH_INTER * D_];
__device__ __half h_sd[(size_t)D_ * SH_INTER];
__device__ __half g_inter[(size_t)E_ * T_ * INTER_];
__device__ __half g_hsh[(size_t)T_ * SH_INTER];

// ---------------- helpers ----------------
__device__ __forceinline__ uint32_t smem_u32(const void* p) {
    uint32_t a;
    asm("{ .reg .u64 t; cvta.to.shared.u64 t, %1; cvt.u32.u64 %0, t; }" : "=r"(a) : "l"(p));
    return a;
}
__device__ __forceinline__ void cp16(uint32_t s, const void* g) {
    asm volatile("cp.async.cg.shared.global [%0], [%1], 16;" :: "r"(s), "l"(g) : "memory");
}
#define CP_COMMIT() asm volatile("cp.async.commit_group;" ::: "memory")
#define CP_WAIT(n)  asm volatile("cp.async.wait_group %0;" :: "n"(n) : "memory")

__device__ __forceinline__ void ldsm4(uint32_t& r0, uint32_t& r1, uint32_t& r2, uint32_t& r3,
                                      uint32_t addr) {
    asm volatile("ldmatrix.sync.aligned.m8n8.x4.shared.b16 {%0,%1,%2,%3}, [%4];"
                 : "=r"(r0), "=r"(r1), "=r"(r2), "=r"(r3) : "r"(addr));
}
__device__ __forceinline__ void mma_f16(float c[4],
                                        uint32_t a0, uint32_t a1, uint32_t a2, uint32_t a3,
                                        uint32_t b0, uint32_t b1) {
    asm volatile(
        "mma.sync.aligned.m16n8k16.row.col.f32.f16.f16.f32 "
        "{%0,%1,%2,%3}, {%4,%5,%6,%7}, {%8,%9}, {%0,%1,%2,%3};"
        : "+f"(c[0]), "+f"(c[1]), "+f"(c[2]), "+f"(c[3])
        : "r"(a0), "r"(a1), "r"(a2), "r"(a3), "r"(b0), "r"(b1));
}
__device__ __forceinline__ float silu_mul(float g, float u) {
    return g / (1.f + expf(-g)) * u;
}
// vector no-return reduction: one red.global.v2 per float2
__device__ __forceinline__ void red_add_v2(float* addr, float a, float b) {
    asm volatile("red.global.add.v2.f32 [%0], {%1, %2};"
                 :: "l"(addr), "f"(a), "f"(b) : "memory");
}

// ---------------- fused fp32 -> fp16 conversion ----------------
#define BIG8   (E_ * INTER_ * D_ / 8)
#define SML8   (SH_INTER * D_ / 8)

__device__ __forceinline__ void cvt_chunk(const float* s, __half* d, int i) {
    float4 v0 = ((const float4*)s)[2 * i];
    float4 v1 = ((const float4*)s)[2 * i + 1];
    ((__half2*)d)[4 * i + 0] = __floats2half2_rn(v0.x, v0.y);
    ((__half2*)d)[4 * i + 1] = __floats2half2_rn(v0.z, v0.w);
    ((__half2*)d)[4 * i + 2] = __floats2half2_rn(v1.x, v1.y);
    ((__half2*)d)[4 * i + 3] = __floats2half2_rn(v1.z, v1.w);
}

// routed gu-side: x, gp, up
#define GUX8 (SML8 + 2 * BIG8)
__global__ void cvt_gux_kernel(const float* __restrict__ x, const float* __restrict__ gp,
                               const float* __restrict__ up) {
    int i = blockIdx.x * blockDim.x + threadIdx.x;
    if (i >= GUX8) return;
    if (i < SML8)                  cvt_chunk(x,  h_x,  i);
    else if (i < SML8 + BIG8)      cvt_chunk(gp, h_gp, i - SML8);
    else                           cvt_chunk(up, h_up, i - SML8 - BIG8);
}
// shared gu-side: sg, su
__global__ void cvt_sgsu_kernel(const float* __restrict__ sg, const float* __restrict__ su) {
    int i = blockIdx.x * blockDim.x + threadIdx.x;
    if (i >= 2 * SML8) return;
    if (i < SML8) cvt_chunk(sg, h_sg, i);
    else          cvt_chunk(su, h_su, i - SML8);
}
// down-side: dp, sd
#define DW8 (BIG8 + SML8)
__global__ void cvt_dw_kernel(const float* __restrict__ dp, const float* __restrict__ sd) {
    int i = blockIdx.x * blockDim.x + threadIdx.x;
    if (i >= DW8) return;
    if (i < BIG8) cvt_chunk(dp, h_dp, i);
    else          cvt_chunk(sd, h_sd, i - BIG8);
}

// ---------------- routing ----------------
__global__ void zero_counts_kernel() {
    if (threadIdx.x < E_) g_cnt[threadIdx.x] = 0;
}

__global__ void route_kernel(const float* __restrict__ x,
                             const float* __restrict__ gw,
                             const float* __restrict__ gb) {
    const int t = blockIdx.x;
    __shared__ float xs[D_];
    __shared__ float sc[E_];
    const int tid = threadIdx.x;  // 128
    const float4* xr = (const float4*)(x + (size_t)t * D_);
    float4* xs4 = (float4*)xs;
    for (int i = tid; i < D_ / 4; i += 128) xs4[i] = xr[i];
    __syncthreads();

    const int warp = tid >> 5, lane = tid & 31;
    for (int e = warp * 4; e < warp * 4 + 4; e++) {
        const float* w = gw + (size_t)e * D_;
        float p = 0.f;
        for (int j = lane; j < D_; j += 32) p += xs[j] * w[j];
        #pragma unroll
        for (int o = 16; o; o >>= 1) p += __shfl_xor_sync(0xffffffffu, p, o);
        if (lane == 0) sc[e] = 1.f / (1.f + expf(-p));
    }
    __syncthreads();

    if (tid == 0) {
        float s[E_];
        #pragma unroll
        for (int e = 0; e < E_; e++) s[e] = sc[e] + gb[e];
        float gsc[NGRP];
        #pragma unroll
        for (int g = 0; g < NGRP; g++) {
            float m1 = -1e30f, m2 = -1e30f;
            #pragma unroll
            for (int j = 0; j < 4; j++) {
                float v = s[g * 4 + j];
                if (v > m1) { m2 = m1; m1 = v; } else if (v > m2) { m2 = v; }
            }
            gsc[g] = m1 + m2;
        }
        int g1 = 0;
        for (int g = 1; g < NGRP; g++) if (gsc[g] > gsc[g1]) g1 = g;
        int g2 = -1;
        for (int g = 0; g < NGRP; g++) {
            if (g == g1) continue;
            if (g2 < 0 || gsc[g] > gsc[g2]) g2 = g;
        }
        float masked[E_];
        #pragma unroll
        for (int e = 0; e < E_; e++) {
            int g = e >> 2;
            masked[e] = (g == g1 || g == g2) ? s[e] : 0.f;
        }
        int idx[K_SEL];
        float w[K_SEL];
        bool used[E_];
        #pragma unroll
        for (int e = 0; e < E_; e++) used[e] = false;
        float wsum = 0.f;
        for (int k = 0; k < K_SEL; k++) {
            int best = -1; float bv = -1e30f;
            for (int e = 0; e < E_; e++) {
                if (used[e]) continue;
                if (masked[e] > bv) { bv = masked[e]; best = e; }
            }
            used[best] = true;
            idx[k] = best;
            w[k] = sc[best];
            wsum += w[k];
        }
        const float scale = RSCALE / wsum;
        for (int k = 0; k < K_SEL; k++) {
            int e = idx[k];
            int pos = atomicAdd(&g_cnt[e], 1);
            g_tok[e * T_ + pos] = t;
            g_wt [e * T_ + pos] = w[k] * scale;
        }
    }
}

// ================================================================
// GEMM 1 (fp16 + ldmatrix + 5-stage single-barrier pipeline)
// zoff selects slice range: z < 16 routed expert, z >= 16 shared half.
// ================================================================
__global__ void __launch_bounds__(256, 2) mma_gu_kernel(int zoff) {
    const int z = zoff + blockIdx.z;
    const bool routed = z < E_;
    const int cnt = routed ? g_cnt[z] : T_;
    const int m0  = blockIdx.y * 128;
    if (m0 >= cnt) return;
    const int n0 = blockIdx.x * 64;

    const __half* Wg;
    const __half* Wu;
    __half* C;
    int ldc, cb;
    if (routed) {
        Wg = h_gp + ((size_t)z * INTER_ + n0) * D_;
        Wu = h_up + ((size_t)z * INTER_ + n0) * D_;
        C = g_inter + (size_t)z * T_ * INTER_;
        ldc = INTER_; cb = n0;
    } else {
        const int h = z - E_;
        Wg = h_sg + ((size_t)h * 512 + n0) * D_;
        Wu = h_su + ((size_t)h * 512 + n0) * D_;
        C = g_hsh;
        ldc = SH_INTER; cb = h * 512 + n0;
    }

    extern __shared__ __half smem[];
    __half* As = smem;
    __half* Bs = smem + NSTG * PLANE;
    const uint32_t sA = smem_u32(As);
    const uint32_t sB = smem_u32(Bs);

    const int tid = threadIdx.x, wid = tid >> 5, lane = tid & 31;
    const int wm = wid >> 2, wn = wid & 3;

    const __half* agl[2]; const __half* bgl[2];
    uint32_t sa[2], sbo[2];
    #pragma unroll
    for (int t = 0; t < 2; t++) {
        int it = tid + 256 * t;
        int row = it >> 2, c4 = it & 3;
        int mm = m0 + row; if (mm > cnt - 1) mm = cnt - 1;
        int ar = routed ? g_tok[z * T_ + mm] : mm;
        agl[t] = h_x + (size_t)ar * D_ + c4 * 8;
        bgl[t] = ((row < 64) ? (Wg + (size_t)row * D_) : (Wu + (size_t)(row - 64) * D_)) + c4 * 8;
        sa[t]  = sA + (uint32_t)(row * LDH + c4 * 8) * 2u;
        sbo[t] = sB + (uint32_t)(row * LDH + c4 * 8) * 2u;
    }

    const int alr = lane & 15, alk = (lane >> 4) * 8;
    const uint32_t a_lsm = sA + (uint32_t)(((wm * 64 + alr) * LDH) + alk) * 2u;
    const int bnr = ((lane >> 4) & 1) * 8 + (lane & 7), bkc = ((lane >> 3) & 1) * 8;
    const uint32_t bg_lsm = sB + (uint32_t)(((wn * 16 + bnr) * LDH) + bkc) * 2u;
    const uint32_t bu_lsm = sB + (uint32_t)(((wn * 16 + bnr + 64) * LDH) + bkc) * 2u;

    float acg[4][2][4], acu[4][2][4];
    #pragma unroll
    for (int mi = 0; mi < 4; mi++)
        #pragma unroll
        for (int nj = 0; nj < 2; nj++)
            #pragma unroll
            for (int r = 0; r < 4; r++) { acg[mi][nj][r] = 0.f; acu[mi][nj][r] = 0.f; }

    const int NS = D_ / 32;   // 32 stages

    // prologue: stages 0..PRE-1, one group each
    #pragma unroll
    for (int p = 0; p < PRE; p++) {
        const uint32_t bo = (uint32_t)(p * ABYTES);
        #pragma unroll
        for (int t = 0; t < 2; t++) { cp16(sa[t] + bo, agl[t] + p * 32); cp16(sbo[t] + bo, bgl[t] + p * 32); }
        CP_COMMIT();
    }

    int buf = 0, pbuf = PRE;   // pbuf = PRE % NSTG
    for (int s = 0; s < NS; s++) {
        CP_WAIT(PRE - 1);
        __syncthreads();
        if (s + PRE < NS) {
            const uint32_t bo = (uint32_t)(pbuf * ABYTES);
            #pragma unroll
            for (int t = 0; t < 2; t++) {
                cp16(sa[t] + bo, agl[t] + (s + PRE) * 32);
                cp16(sbo[t] + bo, bgl[t] + (s + PRE) * 32);
            }
        }
        CP_COMMIT();   // always commit (empty groups keep the count invariant)

        const uint32_t po = (uint32_t)(buf * ABYTES);
        #pragma unroll
        for (int ks = 0; ks < 2; ks++) {
            const uint32_t ko = (uint32_t)(ks * 32);
            uint32_t af[4][4];
            #pragma unroll
            for (int mi = 0; mi < 4; mi++)
                ldsm4(af[mi][0], af[mi][1], af[mi][2], af[mi][3],
                      a_lsm + po + ko + (uint32_t)(mi * 16 * LDH * 2));
            uint32_t bg0a, bg1a, bg0b, bg1b, bu0a, bu1a, bu0b, bu1b;
            ldsm4(bg0a, bg1a, bg0b, bg1b, bg_lsm + po + ko);
            ldsm4(bu0a, bu1a, bu0b, bu1b, bu_lsm + po + ko);
            #pragma unroll
            for (int mi = 0; mi < 4; mi++) {
                mma_f16(acg[mi][0], af[mi][0], af[mi][1], af[mi][2], af[mi][3], bg0a, bg1a);
                mma_f16(acg[mi][1], af[mi][0], af[mi][1], af[mi][2], af[mi][3], bg0b, bg1b);
                mma_f16(acu[mi][0], af[mi][0], af[mi][1], af[mi][2], af[mi][3], bu0a, bu1a);
                mma_f16(acu[mi][1], af[mi][0], af[mi][1], af[mi][2], af[mi][3], bu0b, bu1b);
            }
        }
        buf = (buf == NSTG - 1) ? 0 : buf + 1;
        pbuf = (pbuf == NSTG - 1) ? 0 : pbuf + 1;
    }

    const int q = lane >> 2, c2 = (lane & 3) * 2;
    #pragma unroll
    for (int mi = 0; mi < 4; mi++) {
        const int r0 = m0 + wm * 64 + mi * 16 + q;
        #pragma unroll
        for (int nj = 0; nj < 2; nj++) {
            const int col = cb + wn * 16 + nj * 8 + c2;
            if (r0 < cnt) {
                *(__half2*)(C + (size_t)r0 * ldc + col) =
                    __floats2half2_rn(silu_mul(acg[mi][nj][0], acu[mi][nj][0]),
                                      silu_mul(acg[mi][nj][1], acu[mi][nj][1]));
            }
            if (r0 + 8 < cnt) {
                *(__half2*)(C + (size_t)(r0 + 8) * ldc + col) =
                    __floats2half2_rn(silu_mul(acg[mi][nj][2], acu[mi][nj][2]),
                                      silu_mul(acg[mi][nj][3], acu[mi][nj][3]));
            }
        }
    }
}

// ================================================================
// GEMM 2 (fp16 + ldmatrix + 5-stage single-barrier pipeline)
// epilogue: red.global.add.v2.f32 (vector no-return reductions)
// ================================================================
__global__ void __launch_bounds__(256, 2) mma_down_kernel(int zoff, float* __restrict__ out) {
    const int z = zoff + blockIdx.z;
    const bool routed = z < E_;
    const int cnt = routed ? g_cnt[z] : T_;
    const int m0  = blockIdx.y * 128;
    if (m0 >= cnt) return;
    const int n0 = blockIdx.x * 128;

    const __half* A;
    const __half* W;
    int lda, ldw;
    if (routed) {
        A = g_inter + (size_t)z * T_ * INTER_; lda = INTER_;
        W = h_dp + (size_t)z * D_ * INTER_;    ldw = INTER_;
    } else {
        const int h = z - E_;
        A = g_hsh + (size_t)h * 512; lda = SH_INTER;
        W = h_sd  + (size_t)h * 512; ldw = SH_INTER;
    }

    extern __shared__ __half smem[];
    __half* As = smem;
    __half* Bs = smem + NSTG * PLANE;
    const uint32_t sA = smem_u32(As);
    const uint32_t sB = smem_u32(Bs);

    const int tid = threadIdx.x, wid = tid >> 5, lane = tid & 31;
    const int wm = wid >> 2, wn = wid & 3;

    const __half* agl[2]; const __half* bgl[2];
    uint32_t sa[2], sbo[2];
    #pragma unroll
    for (int t = 0; t < 2; t++) {
        int it = tid + 256 * t;
        int row = it >> 2, c4 = it & 3;
        int mm = m0 + row; if (mm > cnt - 1) mm = cnt - 1;
        agl[t] = A + (size_t)mm * lda + c4 * 8;
        bgl[t] = W + (size_t)(n0 + row) * ldw + c4 * 8;
        sa[t]  = sA + (uint32_t)(row * LDH + c4 * 8) * 2u;
        sbo[t] = sB + (uint32_t)(row * LDH + c4 * 8) * 2u;
    }

    const int alr = lane & 15, alk = (lane >> 4) * 8;
    const uint32_t a_lsm = sA + (uint32_t)(((wm * 64 + alr) * LDH) + alk) * 2u;
    const int bnr = ((lane >> 4) & 1) * 8 + (lane & 7), bkc = ((lane >> 3) & 1) * 8;
    const uint32_t b_lsm = sB + (uint32_t)(((wn * 32 + bnr) * LDH) + bkc) * 2u;

    float acc[4][4][4];
    #pragma unroll
    for (int mi = 0; mi < 4; mi++)
        #pragma unroll
        for (int nj = 0; nj < 4; nj++)
            #pragma unroll
            for (int r = 0; r < 4; r++) acc[mi][nj][r] = 0.f;

    const int NS = INTER_ / 32;   // 16 stages

    #pragma unroll
    for (int p = 0; p < PRE; p++) {
        const uint32_t bo = (uint32_t)(p * ABYTES);
        #pragma unroll
        for (int t = 0; t < 2; t++) { cp16(sa[t] + bo, agl[t] + p * 32); cp16(sbo[t] + bo, bgl[t] + p * 32); }
        CP_COMMIT();
    }

    int buf = 0, pbuf = PRE;
    for (int s = 0; s < NS; s++) {
        CP_WAIT(PRE - 1);
        __syncthreads();
        if (s + PRE < NS) {
            const uint32_t bo = (uint32_t)(pbuf * ABYTES);
            #pragma unroll
            for (int t = 0; t < 2; t++) {
                cp16(sa[t] + bo, agl[t] + (s + PRE) * 32);
                cp16(sbo[t] + bo, bgl[t] + (s + PRE) * 32);
            }
        }
        CP_COMMIT();

        const uint32_t po = (uint32_t)(buf * ABYTES);
        #pragma unroll
        for (int ks = 0; ks < 2; ks++) {
            const uint32_t ko = (uint32_t)(ks * 32);
            uint32_t af[4][4];
            #pragma unroll
            for (int mi = 0; mi < 4; mi++)
                ldsm4(af[mi][0], af[mi][1], af[mi][2], af[mi][3],
                      a_lsm + po + ko + (uint32_t)(mi * 16 * LDH * 2));
            uint32_t b[4][2];
            ldsm4(b[0][0], b[0][1], b[1][0], b[1][1], b_lsm + po + ko);
            ldsm4(b[2][0], b[2][1], b[3][0], b[3][1], b_lsm + po + ko + (uint32_t)(16 * LDH * 2));
            #pragma unroll
            for (int nj = 0; nj < 4; nj++)
                #pragma unroll
                for (int mi = 0; mi < 4; mi++)
                    mma_f16(acc[mi][nj], af[mi][0], af[mi][1], af[mi][2], af[mi][3],
                            b[nj][0], b[nj][1]);
        }
        buf = (buf == NSTG - 1) ? 0 : buf + 1;
        pbuf = (pbuf == NSTG - 1) ? 0 : pbuf + 1;
    }

    const int q = lane >> 2, c2 = (lane & 3) * 2;
    #pragma unroll
    for (int mi = 0; mi < 4; mi++) {
        #pragma unroll
        for (int half_ = 0; half_ < 2; half_++) {
            const int m = m0 + wm * 64 + mi * 16 + q + half_ * 8;
            if (m >= cnt) continue;
            const int   tok = routed ? g_tok[z * T_ + m] : m;
            const float wt  = routed ? g_wt [z * T_ + m] : 1.f;
            float* op = out + (size_t)tok * D_;
            #pragma unroll
            for (int nj = 0; nj < 4; nj++) {
                const int col = n0 + wn * 32 + nj * 8 + c2;
                red_add_v2(op + col, wt * acc[mi][nj][half_ * 2 + 0],
                                     wt * acc[mi][nj][half_ * 2 + 1]);
            }
        }
    }
}

// ---------------- launch (dual-pipeline fork/join, graph-capturable) ----------------
extern "C" void kernel_launch(void* const* d_in, const int* in_sizes, int n_in,
                              void* d_out, int out_size) {
    const float* x  = (const float*)d_in[0];
    const float* gw = (const float*)d_in[2];
    const float* gb = (const float*)d_in[3];
    const float* gp = (const float*)d_in[4];
    const float* up = (const float*)d_in[5];
    const float* dp = (const float*)d_in[6];
    const float* sg = (const float*)d_in[7];
    const float* su = (const float*)d_in[8];
    const float* sd = (const float*)d_in[9];
    float* out = (float*)d_out;

    cudaFuncSetAttribute(mma_gu_kernel,   cudaFuncAttributeMaxDynamicSharedMemorySize, SMEM_BYTES);
    cudaFuncSetAttribute(mma_down_kernel, cudaFuncAttributeMaxDynamicSharedMemorySize, SMEM_BYTES);

    cudaStream_t s1, s2, s3;
    cudaStreamCreateWithFlags(&s1, cudaStreamNonBlocking);
    cudaStreamCreateWithFlags(&s2, cudaStreamNonBlocking);
    cudaStreamCreateWithFlags(&s3, cudaStreamNonBlocking);
    cudaEvent_t eF, eDW, eRoute, eGUX, eShared;
    cudaEventCreateWithFlags(&eF,     cudaEventDisableTiming);
    cudaEventCreateWithFlags(&eDW,    cudaEventDisableTiming);
    cudaEventCreateWithFlags(&eRoute, cudaEventDisableTiming);
    cudaEventCreateWithFlags(&eGUX,   cudaEventDisableTiming);
    cudaEventCreateWithFlags(&eShared,cudaEventDisableTiming);

    const int NB = 256;

    // fork
    cudaEventRecord(eF, 0);
    cudaStreamWaitEvent(s1, eF, 0);
    cudaStreamWaitEvent(s2, eF, 0);
    cudaStreamWaitEvent(s3, eF, 0);

    // s1: memset + down-side weight convert (hidden under gu stage)
    cudaMemsetAsync(out, 0, (size_t)T_ * D_ * sizeof(float), s1);
    cvt_dw_kernel<<<(DW8 + NB - 1) / NB, NB, 0, s1>>>(dp, sd);
    cudaEventRecord(eDW, s1);

    // s2: routing (hidden under gu-side convert)
    zero_counts_kernel<<<1, 32, 0, s2>>>();
    route_kernel<<<T_, 128, 0, s2>>>(x, gw, gb);
    cudaEventRecord(eRoute, s2);

    // s0 (capture stream): routed pipeline
    cvt_gux_kernel<<<(GUX8 + NB - 1) / NB, NB>>>(x, gp, up);
    cudaEventRecord(eGUX, 0);
    cudaStreamWaitEvent(0, eRoute, 0);
    mma_gu_kernel<<<dim3(INTER_ / 64, T_ / 128, E_), 256, SMEM_BYTES>>>(0);
    cudaStreamWaitEvent(0, eDW, 0);
    mma_down_kernel<<<dim3(D_ / 128, T_ / 128, E_), 256, SMEM_BYTES>>>(0, out);

    // s3: shared pipeline (concurrent with routed pipeline)
    cvt_sgsu_kernel<<<(2 * SML8 + NB - 1) / NB, NB, 0, s3>>>(sg, su);
    cudaStreamWaitEvent(s3, eGUX, 0);                // needs converted x
    mma_gu_kernel<<<dim3(8, T_ / 128, 2), 256, SMEM_BYTES, s3>>>(E_);
    cudaStreamWaitEvent(s3, eDW, 0);                 // needs sd + memset
    mma_down_kernel<<<dim3(D_ / 128, T_ / 128, 2), 256, SMEM_BYTES, s3>>>(E_, out);
    cudaEventRecord(eShared, s3);

    // join shared pipeline back into capture stream
    cudaStreamWaitEvent(0, eShared, 0);

    cudaEventDestroy(eF);
    cudaEventDestroy(eDW);
    cudaEventDestroy(eRoute);
    cudaEventDestroy(eGUX);
    cudaEventDestroy(eShared);
    cudaStreamDestroy(s1);
    cudaStreamDestroy(s2);
    cudaStreamDestroy(s3);
}

// round 16
// speedup vs baseline: 1.1766x; 1.0134x over previous
#include <cuda_runtime.h>
#include <cuda_fp16.h>
#include <math.h>
#include <stdint.h>

// Problem constants
#define T_       1024
#define D_       1024
#define E_       16
#define K_SEL    4
#define NGRP     4
#define INTER_   512
#define SH_INTER 1024
#define RSCALE   2.5f

#define LDH   40                      // smem row stride in halves (80B, LDSM conflict-free)
#define PLANE (128 * LDH)             // halves per plane-stage
#define ABYTES (PLANE * 2)            // 10240 B
#define NSTG  5                       // 5-deep cp.async ring
#define PRE   4                       // prologue depth (NSTG-1)
#define SMEM_BYTES (2 * NSTG * ABYTES)   // 102400 B

// ---------------- device scratch (fp16 operands) ----------------
__device__ int    g_cnt[E_];
__device__ int    g_tok[E_ * T_];
__device__ float  g_wt [E_ * T_];
__device__ __half h_x [(size_t)T_ * D_];
__device__ __half h_gp[(size_t)E_ * INTER_ * D_];
__device__ __half h_up[(size_t)E_ * INTER_ * D_];
__device__ __half h_dp[(size_t)E_ * D_ * INTER_];
__device__ __half h_sg[(size_t)SH_INTER * D_];
__device__ __half h_su[(size_t)SH_INTER * D_];
__device__ __half h_sd[(size_t)D_ * SH_INTER];
__device__ __half g_inter[(size_t)E_ * T_ * INTER_];
__device__ __half g_hsh[(size_t)T_ * SH_INTER];

// ---------------- helpers ----------------
__device__ __forceinline__ uint32_t smem_u32(const void* p) {
    uint32_t a;
    asm("{ .reg .u64 t; cvta.to.shared.u64 t, %1; cvt.u32.u64 %0, t; }" : "=r"(a) : "l"(p));
    return a;
}
__device__ __forceinline__ void cp16(uint32_t s, const void* g) {
    asm volatile("cp.async.cg.shared.global [%0], [%1], 16;" :: "r"(s), "l"(g) : "memory");
}
#define CP_COMMIT() asm volatile("cp.async.commit_group;" ::: "memory")
#define CP_WAIT(n)  asm volatile("cp.async.wait_group %0;" :: "n"(n) : "memory")

__device__ __forceinline__ void ldsm4(uint32_t& r0, uint32_t& r1, uint32_t& r2, uint32_t& r3,
                                      uint32_t addr) {
    asm volatile("ldmatrix.sync.aligned.m8n8.x4.shared.b16 {%0,%1,%2,%3}, [%4];"
                 : "=r"(r0), "=r"(r1), "=r"(r2), "=r"(r3) : "r"(addr));
}
__device__ __forceinline__ void mma_f16(float c[4],
                                        uint32_t a0, uint32_t a1, uint32_t a2, uint32_t a3,
                                        uint32_t b0, uint32_t b1) {
    asm volatile(
        "mma.sync.aligned.m16n8k16.row.col.f32.f16.f16.f32 "
        "{%0,%1,%2,%3}, {%4,%5,%6,%7}, {%8,%9}, {%0,%1,%2,%3};"
        : "+f"(c[0]), "+f"(c[1]), "+f"(c[2]), "+f"(c[3])
        : "r"(a0), "r"(a1), "r"(a2), "r"(a3), "r"(b0), "r"(b1));
}
__device__ __forceinline__ float silu_mul(float g, float u) {
    return g / (1.f + expf(-g)) * u;
}
// vector no-return reduction: one red.global.v2 per float2
__device__ __forceinline__ void red_add_v2(float* addr, float a, float b) {
    asm volatile("red.global.add.v2.f32 [%0], {%1, %2};"
                 :: "l"(addr), "f"(a), "f"(b) : "memory");
}

// ---------------- fused fp32 -> fp16 conversion ----------------
#define BIG8   (E_ * INTER_ * D_ / 8)
#define SML8   (SH_INTER * D_ / 8)

__device__ __forceinline__ void cvt_chunk(const float* s, __half* d, int i) {
    float4 v0 = ((const float4*)s)[2 * i];
    float4 v1 = ((const float4*)s)[2 * i + 1];
    ((__half2*)d)[4 * i + 0] = __floats2half2_rn(v0.x, v0.y);
    ((__half2*)d)[4 * i + 1] = __floats2half2_rn(v0.z, v0.w);
    ((__half2*)d)[4 * i + 2] = __floats2half2_rn(v1.x, v1.y);
    ((__half2*)d)[4 * i + 3] = __floats2half2_rn(v1.z, v1.w);
}

// x only (tiny, unblocks both gu pipelines' A operand)
__global__ void cvt_x_kernel(const float* __restrict__ x) {
    int i = blockIdx.x * blockDim.x + threadIdx.x;
    if (i < SML8) cvt_chunk(x, h_x, i);
}
// routed gu weights: gp, up
#define WGU8 (2 * BIG8)
__global__ void cvt_wgu_kernel(const float* __restrict__ gp, const float* __restrict__ up) {
    int i = blockIdx.x * blockDim.x + threadIdx.x;
    if (i >= WGU8) return;
    if (i < BIG8) cvt_chunk(gp, h_gp, i);
    else          cvt_chunk(up, h_up, i - BIG8);
}
// shared gu-side: sg, su
__global__ void cvt_sgsu_kernel(const float* __restrict__ sg, const float* __restrict__ su) {
    int i = blockIdx.x * blockDim.x + threadIdx.x;
    if (i >= 2 * SML8) return;
    if (i < SML8) cvt_chunk(sg, h_sg, i);
    else          cvt_chunk(su, h_su, i - SML8);
}
// down-side: dp, sd
#define DW8 (BIG8 + SML8)
__global__ void cvt_dw_kernel(const float* __restrict__ dp, const float* __restrict__ sd) {
    int i = blockIdx.x * blockDim.x + threadIdx.x;
    if (i >= DW8) return;
    if (i < BIG8) cvt_chunk(dp, h_dp, i);
    else          cvt_chunk(sd, h_sd, i - BIG8);
}

// ---------------- routing ----------------
__global__ void zero_counts_kernel() {
    if (threadIdx.x < E_) g_cnt[threadIdx.x] = 0;
}

__global__ void route_kernel(const float* __restrict__ x,
                             const float* __restrict__ gw,
                             const float* __restrict__ gb) {
    const int t = blockIdx.x;
    __shared__ float xs[D_];
    __shared__ float sc[E_];
    const int tid = threadIdx.x;  // 128
    const float4* xr = (const float4*)(x + (size_t)t * D_);
    float4* xs4 = (float4*)xs;
    for (int i = tid; i < D_ / 4; i += 128) xs4[i] = xr[i];
    __syncthreads();

    const int warp = tid >> 5, lane = tid & 31;
    for (int e = warp * 4; e < warp * 4 + 4; e++) {
        const float* w = gw + (size_t)e * D_;
        float p = 0.f;
        for (int j = lane; j < D_; j += 32) p += xs[j] * w[j];
        #pragma unroll
        for (int o = 16; o; o >>= 1) p += __shfl_xor_sync(0xffffffffu, p, o);
        if (lane == 0) sc[e] = 1.f / (1.f + expf(-p));
    }
    __syncthreads();

    if (tid == 0) {
        float s[E_];
        #pragma unroll
        for (int e = 0; e < E_; e++) s[e] = sc[e] + gb[e];
        float gsc[NGRP];
        #pragma unroll
        for (int g = 0; g < NGRP; g++) {
            float m1 = -1e30f, m2 = -1e30f;
            #pragma unroll
            for (int j = 0; j < 4; j++) {
                float v = s[g * 4 + j];
                if (v > m1) { m2 = m1; m1 = v; } else if (v > m2) { m2 = v; }
            }
            gsc[g] = m1 + m2;
        }
        int g1 = 0;
        for (int g = 1; g < NGRP; g++) if (gsc[g] > gsc[g1]) g1 = g;
        int g2 = -1;
        for (int g = 0; g < NGRP; g++) {
            if (g == g1) continue;
            if (g2 < 0 || gsc[g] > gsc[g2]) g2 = g;
        }
        float masked[E_];
        #pragma unroll
        for (int e = 0; e < E_; e++) {
            int g = e >> 2;
            masked[e] = (g == g1 || g == g2) ? s[e] : 0.f;
        }
        int idx[K_SEL];
        float w[K_SEL];
        bool used[E_];
        #pragma unroll
        for (int e = 0; e < E_; e++) used[e] = false;
        float wsum = 0.f;
        for (int k = 0; k < K_SEL; k++) {
            int best = -1; float bv = -1e30f;
            for (int e = 0; e < E_; e++) {
                if (used[e]) continue;
                if (masked[e] > bv) { bv = masked[e]; best = e; }
            }
            used[best] = true;
            idx[k] = best;
            w[k] = sc[best];
            wsum += w[k];
        }
        const float scale = RSCALE / wsum;
        for (int k = 0; k < K_SEL; k++) {
            int e = idx[k];
            int pos = atomicAdd(&g_cnt[e], 1);
            g_tok[e * T_ + pos] = t;
            g_wt [e * T_ + pos] = w[k] * scale;
        }
    }
}

// ================================================================
// GEMM 1 (fp16 + ldmatrix + 5-stage single-barrier pipeline)
// zoff selects slice range: z < 16 routed expert, z >= 16 shared half.
// ================================================================
__global__ void __launch_bounds__(256, 2) mma_gu_kernel(int zoff) {
    const int z = zoff + blockIdx.z;
    const bool routed = z < E_;
    const int cnt = routed ? g_cnt[z] : T_;
    const int m0  = blockIdx.y * 128;
    if (m0 >= cnt) return;
    const int n0 = blockIdx.x * 64;

    const __half* Wg;
    const __half* Wu;
    __half* C;
    int ldc, cb;
    if (routed) {
        Wg = h_gp + ((size_t)z * INTER_ + n0) * D_;
        Wu = h_up + ((size_t)z * INTER_ + n0) * D_;
        C = g_inter + (size_t)z * T_ * INTER_;
        ldc = INTER_; cb = n0;
    } else {
        const int h = z - E_;
        Wg = h_sg + ((size_t)h * 512 + n0) * D_;
        Wu = h_su + ((size_t)h * 512 + n0) * D_;
        C = g_hsh;
        ldc = SH_INTER; cb = h * 512 + n0;
    }

    extern __shared__ __half smem[];
    __half* As = smem;
    __half* Bs = smem + NSTG * PLANE;
    const uint32_t sA = smem_u32(As);
    const uint32_t sB = smem_u32(Bs);

    const int tid = threadIdx.x, wid = tid >> 5, lane = tid & 31;
    const int wm = wid >> 2, wn = wid & 3;

    const __half* agl[2]; const __half* bgl[2];
    uint32_t sa[2], sbo[2];
    #pragma unroll
    for (int t = 0; t < 2; t++) {
        int it = tid + 256 * t;
        int row = it >> 2, c4 = it & 3;
        int mm = m0 + row; if (mm > cnt - 1) mm = cnt - 1;
        int ar = routed ? g_tok[z * T_ + mm] : mm;
        agl[t] = h_x + (size_t)ar * D_ + c4 * 8;
        bgl[t] = ((row < 64) ? (Wg + (size_t)row * D_) : (Wu + (size_t)(row - 64) * D_)) + c4 * 8;
        sa[t]  = sA + (uint32_t)(row * LDH + c4 * 8) * 2u;
        sbo[t] = sB + (uint32_t)(row * LDH + c4 * 8) * 2u;
    }

    const int alr = lane & 15, alk = (lane >> 4) * 8;
    const uint32_t a_lsm = sA + (uint32_t)(((wm * 64 + alr) * LDH) + alk) * 2u;
    const int bnr = ((lane >> 4) & 1) * 8 + (lane & 7), bkc = ((lane >> 3) & 1) * 8;
    const uint32_t bg_lsm = sB + (uint32_t)(((wn * 16 + bnr) * LDH) + bkc) * 2u;
    const uint32_t bu_lsm = sB + (uint32_t)(((wn * 16 + bnr + 64) * LDH) + bkc) * 2u;

    float acg[4][2][4], acu[4][2][4];
    #pragma unroll
    for (int mi = 0; mi < 4; mi++)
        #pragma unroll
        for (int nj = 0; nj < 2; nj++)
            #pragma unroll
            for (int r = 0; r < 4; r++) { acg[mi][nj][r] = 0.f; acu[mi][nj][r] = 0.f; }

    const int NS = D_ / 32;   // 32 stages

    #pragma unroll
    for (int p = 0; p < PRE; p++) {
        const uint32_t bo = (uint32_t)(p * ABYTES);
        #pragma unroll
        for (int t = 0; t < 2; t++) { cp16(sa[t] + bo, agl[t] + p * 32); cp16(sbo[t] + bo, bgl[t] + p * 32); }
        CP_COMMIT();
    }

    int buf = 0, pbuf = PRE;
    for (int s = 0; s < NS; s++) {
        CP_WAIT(PRE - 1);
        __syncthreads();
        if (s + PRE < NS) {
            const uint32_t bo = (uint32_t)(pbuf * ABYTES);
            #pragma unroll
            for (int t = 0; t < 2; t++) {
                cp16(sa[t] + bo, agl[t] + (s + PRE) * 32);
                cp16(sbo[t] + bo, bgl[t] + (s + PRE) * 32);
            }
        }
        CP_COMMIT();

        const uint32_t po = (uint32_t)(buf * ABYTES);
        #pragma unroll
        for (int ks = 0; ks < 2; ks++) {
            const uint32_t ko = (uint32_t)(ks * 32);
            uint32_t af[4][4];
            #pragma unroll
            for (int mi = 0; mi < 4; mi++)
                ldsm4(af[mi][0], af[mi][1], af[mi][2], af[mi][3],
                      a_lsm + po + ko + (uint32_t)(mi * 16 * LDH * 2));
            uint32_t bg0a, bg1a, bg0b, bg1b, bu0a, bu1a, bu0b, bu1b;
            ldsm4(bg0a, bg1a, bg0b, bg1b, bg_lsm + po + ko);
            ldsm4(bu0a, bu1a, bu0b, bu1b, bu_lsm + po + ko);
            #pragma unroll
            for (int mi = 0; mi < 4; mi++) {
                mma_f16(acg[mi][0], af[mi][0], af[mi][1], af[mi][2], af[mi][3], bg0a, bg1a);
                mma_f16(acg[mi][1], af[mi][0], af[mi][1], af[mi][2], af[mi][3], bg0b, bg1b);
                mma_f16(acu[mi][0], af[mi][0], af[mi][1], af[mi][2], af[mi][3], bu0a, bu1a);
                mma_f16(acu[mi][1], af[mi][0], af[mi][1], af[mi][2], af[mi][3], bu0b, bu1b);
            }
        }
        buf = (buf == NSTG - 1) ? 0 : buf + 1;
        pbuf = (pbuf == NSTG - 1) ? 0 : pbuf + 1;
    }

    const int q = lane >> 2, c2 = (lane & 3) * 2;
    #pragma unroll
    for (int mi = 0; mi < 4; mi++) {
        const int r0 = m0 + wm * 64 + mi * 16 + q;
        #pragma unroll
        for (int nj = 0; nj < 2; nj++) {
            const int col = cb + wn * 16 + nj * 8 + c2;
            if (r0 < cnt) {
                *(__half2*)(C + (size_t)r0 * ldc + col) =
                    __floats2half2_rn(silu_mul(acg[mi][nj][0], acu[mi][nj][0]),
                                      silu_mul(acg[mi][nj][1], acu[mi][nj][1]));
            }
            if (r0 + 8 < cnt) {
                *(__half2*)(C + (size_t)(r0 + 8) * ldc + col) =
                    __floats2half2_rn(silu_mul(acg[mi][nj][2], acu[mi][nj][2]),
                                      silu_mul(acg[mi][nj][3], acu[mi][nj][3]));
            }
        }
    }
}

// ================================================================
// GEMM 2 (fp16 + ldmatrix + 5-stage single-barrier pipeline)
// epilogue: red.global.add.v2.f32 (vector no-return reductions)
// ================================================================
__global__ void __launch_bounds__(256, 2) mma_down_kernel(int zoff, float* __restrict__ out) {
    const int z = zoff + blockIdx.z;
    const bool routed = z < E_;
    const int cnt = routed ? g_cnt[z] : T_;
    const int m0  = blockIdx.y * 128;
    if (m0 >= cnt) return;
    const int n0 = blockIdx.x * 128;

    const __half* A;
    const __half* W;
    int lda, ldw;
    if (routed) {
        A = g_inter + (size_t)z * T_ * INTER_; lda = INTER_;
        W = h_dp + (size_t)z * D_ * INTER_;    ldw = INTER_;
    } else {
        const int h = z - E_;
        A = g_hsh + (size_t)h * 512; lda = SH_INTER;
        W = h_sd  + (size_t)h * 512; ldw = SH_INTER;
    }

    extern __shared__ __half smem[];
    __half* As = smem;
    __half* Bs = smem + NSTG * PLANE;
    const uint32_t sA = smem_u32(As);
    const uint32_t sB = smem_u32(Bs);

    const int tid = threadIdx.x, wid = tid >> 5, lane = tid & 31;
    const int wm = wid >> 2, wn = wid & 3;

    const __half* agl[2]; const __half* bgl[2];
    uint32_t sa[2], sbo[2];
    #pragma unroll
    for (int t = 0; t < 2; t++) {
        int it = tid + 256 * t;
        int row = it >> 2, c4 = it & 3;
        int mm = m0 + row; if (mm > cnt - 1) mm = cnt - 1;
        agl[t] = A + (size_t)mm * lda + c4 * 8;
        bgl[t] = W + (size_t)(n0 + row) * ldw + c4 * 8;
        sa[t]  = sA + (uint32_t)(row * LDH + c4 * 8) * 2u;
        sbo[t] = sB + (uint32_t)(row * LDH + c4 * 8) * 2u;
    }

    const int alr = lane & 15, alk = (lane >> 4) * 8;
    const uint32_t a_lsm = sA + (uint32_t)(((wm * 64 + alr) * LDH) + alk) * 2u;
    const int bnr = ((lane >> 4) & 1) * 8 + (lane & 7), bkc = ((lane >> 3) & 1) * 8;
    const uint32_t b_lsm = sB + (uint32_t)(((wn * 32 + bnr) * LDH) + bkc) * 2u;

    float acc[4][4][4];
    #pragma unroll
    for (int mi = 0; mi < 4; mi++)
        #pragma unroll
        for (int nj = 0; nj < 4; nj++)
            #pragma unroll
            for (int r = 0; r < 4; r++) acc[mi][nj][r] = 0.f;

    const int NS = INTER_ / 32;   // 16 stages

    #pragma unroll
    for (int p = 0; p < PRE; p++) {
        const uint32_t bo = (uint32_t)(p * ABYTES);
        #pragma unroll
        for (int t = 0; t < 2; t++) { cp16(sa[t] + bo, agl[t] + p * 32); cp16(sbo[t] + bo, bgl[t] + p * 32); }
        CP_COMMIT();
    }

    int buf = 0, pbuf = PRE;
    for (int s = 0; s < NS; s++) {
        CP_WAIT(PRE - 1);
        __syncthreads();
        if (s + PRE < NS) {
            const uint32_t bo = (uint32_t)(pbuf * ABYTES);
            #pragma unroll
            for (int t = 0; t < 2; t++) {
                cp16(sa[t] + bo, agl[t] + (s + PRE) * 32);
                cp16(sbo[t] + bo, bgl[t] + (s + PRE) * 32);
            }
        }
        CP_COMMIT();

        const uint32_t po = (uint32_t)(buf * ABYTES);
        #pragma unroll
        for (int ks = 0; ks < 2; ks++) {
            const uint32_t ko = (uint32_t)(ks * 32);
            uint32_t af[4][4];
            #pragma unroll
            for (int mi = 0; mi < 4; mi++)
                ldsm4(af[mi][0], af[mi][1], af[mi][2], af[mi][3],
                      a_lsm + po + ko + (uint32_t)(mi * 16 * LDH * 2));
            uint32_t b[4][2];
            ldsm4(b[0][0], b[0][1], b[1][0], b[1][1], b_lsm + po + ko);
            ldsm4(b[2][0], b[2][1], b[3][0], b[3][1], b_lsm + po + ko + (uint32_t)(16 * LDH * 2));
            #pragma unroll
            for (int nj = 0; nj < 4; nj++)
                #pragma unroll
                for (int mi = 0; mi < 4; mi++)
                    mma_f16(acc[mi][nj], af[mi][0], af[mi][1], af[mi][2], af[mi][3],
                            b[nj][0], b[nj][1]);
        }
        buf = (buf == NSTG - 1) ? 0 : buf + 1;
        pbuf = (pbuf == NSTG - 1) ? 0 : pbuf + 1;
    }

    const int q = lane >> 2, c2 = (lane & 3) * 2;
    #pragma unroll
    for (int mi = 0; mi < 4; mi++) {
        #pragma unroll
        for (int half_ = 0; half_ < 2; half_++) {
            const int m = m0 + wm * 64 + mi * 16 + q + half_ * 8;
            if (m >= cnt) continue;
            const int   tok = routed ? g_tok[z * T_ + m] : m;
            const float wt  = routed ? g_wt [z * T_ + m] : 1.f;
            float* op = out + (size_t)tok * D_;
            #pragma unroll
            for (int nj = 0; nj < 4; nj++) {
                const int col = n0 + wn * 32 + nj * 8 + c2;
                red_add_v2(op + col, wt * acc[mi][nj][half_ * 2 + 0],
                                     wt * acc[mi][nj][half_ * 2 + 1]);
            }
        }
    }
}

// ---------------- launch (early-x convert + dual-pipeline fork/join) ----------------
extern "C" void kernel_launch(void* const* d_in, const int* in_sizes, int n_in,
                              void* d_out, int out_size) {
    const float* x  = (const float*)d_in[0];
    const float* gw = (const float*)d_in[2];
    const float* gb = (const float*)d_in[3];
    const float* gp = (const float*)d_in[4];
    const float* up = (const float*)d_in[5];
    const float* dp = (const float*)d_in[6];
    const float* sg = (const float*)d_in[7];
    const float* su = (const float*)d_in[8];
    const float* sd = (const float*)d_in[9];
    float* out = (float*)d_out;

    cudaFuncSetAttribute(mma_gu_kernel,   cudaFuncAttributeMaxDynamicSharedMemorySize, SMEM_BYTES);
    cudaFuncSetAttribute(mma_down_kernel, cudaFuncAttributeMaxDynamicSharedMemorySize, SMEM_BYTES);

    cudaStream_t s1, s2, s3;
    cudaStreamCreateWithFlags(&s1, cudaStreamNonBlocking);
    cudaStreamCreateWithFlags(&s2, cudaStreamNonBlocking);
    cudaStreamCreateWithFlags(&s3, cudaStreamNonBlocking);
    cudaEvent_t eF, eDW, eRoute, eX, eShared;
    cudaEventCreateWithFlags(&eF,     cudaEventDisableTiming);
    cudaEventCreateWithFlags(&eDW,    cudaEventDisableTiming);
    cudaEventCreateWithFlags(&eRoute, cudaEventDisableTiming);
    cudaEventCreateWithFlags(&eX,     cudaEventDisableTiming);
    cudaEventCreateWithFlags(&eShared,cudaEventDisableTiming);

    const int NB = 256;

    // fork
    cudaEventRecord(eF, 0);
    cudaStreamWaitEvent(s1, eF, 0);
    cudaStreamWaitEvent(s2, eF, 0);
    cudaStreamWaitEvent(s3, eF, 0);

    // s1: memset + down-side weight convert (hidden under gu stage)
    cudaMemsetAsync(out, 0, (size_t)T_ * D_ * sizeof(float), s1);
    cvt_dw_kernel<<<(DW8 + NB - 1) / NB, NB, 0, s1>>>(dp, sd);
    cudaEventRecord(eDW, s1);

    // s2: routing (hidden under gu-side converts)
    zero_counts_kernel<<<1, 32, 0, s2>>>();
    route_kernel<<<T_, 128, 0, s2>>>(x, gw, gb);
    cudaEventRecord(eRoute, s2);

    // s0 (capture stream): x convert first (unblocks shared pipeline early),
    // then the big routed gu-weight convert, then routed gu + down.
    cvt_x_kernel<<<(SML8 + NB - 1) / NB, NB>>>(x);
    cudaEventRecord(eX, 0);
    cvt_wgu_kernel<<<(WGU8 + NB - 1) / NB, NB>>>(gp, up);
    cudaStreamWaitEvent(0, eRoute, 0);
    mma_gu_kernel<<<dim3(INTER_ / 64, T_ / 128, E_), 256, SMEM_BYTES>>>(0);
    cudaStreamWaitEvent(0, eDW, 0);
    mma_down_kernel<<<dim3(D_ / 128, T_ / 128, E_), 256, SMEM_BYTES>>>(0, out);

    // s3: shared pipeline — starts as soon as x + sg/su are converted,
    // overlapping the (DRAM-bound) routed weight convert.
    cvt_sgsu_kernel<<<(2 * SML8 + NB - 1) / NB, NB, 0, s3>>>(sg, su);
    cudaStreamWaitEvent(s3, eX, 0);
    mma_gu_kernel<<<dim3(8, T_ / 128, 2), 256, SMEM_BYTES, s3>>>(E_);
    cudaStreamWaitEvent(s3, eDW, 0);
    mma_down_kernel<<<dim3(D_ / 128, T_ / 128, 2), 256, SMEM_BYTES, s3>>>(E_, out);
    cudaEventRecord(eShared, s3);

    // join shared pipeline back into capture stream
    cudaStreamWaitEvent(0, eShared, 0);

    cudaEventDestroy(eF);
    cudaEventDestroy(eDW);
    cudaEventDestroy(eRoute);
    cudaEventDestroy(eX);
    cudaEventDestroy(eShared);
    cudaStreamDestroy(s1);
    cudaStreamDestroy(s2);
    cudaStreamDestroy(s3);
}